// round 5
// baseline (speedup 1.0000x reference)
#include <cuda_runtime.h>

#define B_  32
#define C_  64
#define H_  128
#define W_  128
#define HW  16384
#define CR  38               // floor(0.6*64)=38, even
#define CIR 26

// fused tile: 64 px wide x 8 rows = 512 px = 128 float4-groups
#define FTW 64
#define FTH 8
#define NG  128              // float4-groups per tile
#define HALO_W 70            // 64+6
#define HALO_H 14            // 8+6

// Scratch (allocation-free rule: __device__ globals)
__device__ unsigned long long g_mask[B_];
__device__ float4 g_maps[B_ * HW];   // {ravg, rmax, iravg, irmax}, 8 MB

// ---------------------------------------------------------------------------
// top-k(CR) rank mask, threads 0..63 cooperate. jax top_k tiebreak: smaller
// index wins ties.
// ---------------------------------------------------------------------------
__device__ __forceinline__ unsigned long long
compute_mask(const float* __restrict__ M, int b, int t,
             float* sm, unsigned long long* smask) {
    if (t == 0) *smask = 0ull;
    if (t < C_) sm[t] = __ldg(M + b * C_ + t);
    __syncthreads();
    if (t < C_) {
        float v = sm[t];
        int rank = 0;
        #pragma unroll
        for (int j = 0; j < C_; j++) {
            float mj = sm[j];
            rank += (mj > v) || (mj == v && j < t);
        }
        if (rank < CR) atomicOr(smask, 1ull << t);
    }
    __syncthreads();
    return *smask;
}

// ---------------------------------------------------------------------------
// Kernel 1: mask + channel reductions, 2-way channel split.
// CTA = 128 float4-groups; threads 0-127 do channels 0-31, 128-255 do 32-63.
// Masked-out entries are exact zeros in the reference -> max init to 0.
// ---------------------------------------------------------------------------
__global__ void __launch_bounds__(256) reduce_kernel(
        const float* __restrict__ x, const float* __restrict__ M) {
    __shared__ float sm[C_];
    __shared__ unsigned long long smask;
    __shared__ float4 part[128][4];      // rs, rm, is, im of upper half

    int t     = threadIdx.x;
    int b     = blockIdx.x >> 5;         // 32 CTAs per batch
    int slice = blockIdx.x & 31;
    int half  = t >> 7;                  // 0 or 1
    int gi    = t & 127;
    int group = slice * 128 + gi;        // float4 pixel-group 0..4095

    unsigned long long mask = compute_mask(M, b, t, sm, &smask);
    if (slice == 0 && t == 0) g_mask[b] = mask;

    const float4* xb = (const float4*)(x + (size_t)b * C_ * HW) + group
                     + half * 32 * (HW / 4);

    float4 rs = {0,0,0,0}, rm = {0,0,0,0};
    float4 is = {0,0,0,0}, im = {0,0,0,0};
    unsigned long long msk = mask >> (half * 32);

    #pragma unroll
    for (int c = 0; c < 32; c++) {
        float4 v = __ldg(xb + c * (HW / 4));
        if ((msk >> c) & 1ull) {
            rs.x += v.x; rs.y += v.y; rs.z += v.z; rs.w += v.w;
            rm.x = fmaxf(rm.x, v.x); rm.y = fmaxf(rm.y, v.y);
            rm.z = fmaxf(rm.z, v.z); rm.w = fmaxf(rm.w, v.w);
        } else {
            is.x += v.x; is.y += v.y; is.z += v.z; is.w += v.w;
            im.x = fmaxf(im.x, v.x); im.y = fmaxf(im.y, v.y);
            im.z = fmaxf(im.z, v.z); im.w = fmaxf(im.w, v.w);
        }
    }

    if (half == 1) {
        part[gi][0] = rs; part[gi][1] = rm;
        part[gi][2] = is; part[gi][3] = im;
    }
    __syncthreads();
    if (half == 0) {
        float4 ors = part[gi][0], orm = part[gi][1];
        float4 ois = part[gi][2], oim = part[gi][3];
        rs.x += ors.x; rs.y += ors.y; rs.z += ors.z; rs.w += ors.w;
        is.x += ois.x; is.y += ois.y; is.z += ois.z; is.w += ois.w;
        rm.x = fmaxf(rm.x, orm.x); rm.y = fmaxf(rm.y, orm.y);
        rm.z = fmaxf(rm.z, orm.z); rm.w = fmaxf(rm.w, orm.w);
        im.x = fmaxf(im.x, oim.x); im.y = fmaxf(im.y, oim.y);
        im.z = fmaxf(im.z, oim.z); im.w = fmaxf(im.w, oim.w);

        const float kr = 1.0f / (float)CR, ki = 1.0f / (float)CIR;
        float4* mp = g_maps + (size_t)b * HW + group * 4;
        mp[0] = make_float4(rs.x * kr, rm.x, is.x * ki, im.x);
        mp[1] = make_float4(rs.y * kr, rm.y, is.y * ki, im.y);
        mp[2] = make_float4(rs.z * kr, rm.z, is.z * ki, im.z);
        mp[3] = make_float4(rs.w * kr, rm.w, is.w * ki, im.w);
    }
}

// ---------------------------------------------------------------------------
// Kernel 2: fused conv(7x7,pad3)+BN+relu+sigmoid+combine, two-phase CTA.
// Tile 64x8 px. Phase 1: halo->smem, conv from smem, a1/a2 -> smem.
// Phase 2: 2-way channel-split float4 streaming of x -> out.
// ---------------------------------------------------------------------------
__global__ void __launch_bounds__(256) fused_kernel(
        const float* __restrict__ x,
        float* __restrict__ out,
        const float* __restrict__ cw,
        const float* __restrict__ gamma,
        const float* __restrict__ beta,
        const float* __restrict__ mean,
        const float* __restrict__ var) {
    __shared__ float4 smaps[HALO_H][HALO_W];   // 15.3 KB
    __shared__ float sw[98];
    __shared__ float sa1[FTH][FTW];            // 2 KB
    __shared__ float sa2[FTH][FTW];            // 2 KB

    int t = threadIdx.x;
    int tile = blockIdx.x;                  // 0..1023
    int b  = tile >> 5;                     // 32 tiles per batch
    int ti = tile & 31;
    int h0 = (ti >> 1) * FTH;               // 16 tile-rows
    int w0 = (ti & 1) * FTW;                // 2 tile-cols

    if (t < 98) sw[t] = __ldg(cw + t);

    // --- halo load: 14 x 70 float4 (zero outside image) ---
    const float4* mb = g_maps + (size_t)b * HW;
    for (int i = t; i < HALO_H * HALO_W; i += 256) {
        int r  = i / HALO_W;
        int cx = i - r * HALO_W;
        int gh = h0 + r - 3;
        int gw = w0 + cx - 3;
        float4 v = {0,0,0,0};
        if (gh >= 0 && gh < H_ && gw >= 0 && gw < W_)
            v = __ldg(mb + gh * W_ + gw);
        smaps[r][cx] = v;
    }
    __syncthreads();

    // --- phase 1: conv+BN+relu+sigmoid for 2 px/thread ---
    {
        int w  = t & 63;                    // 0..63
        int hh = t >> 6;                    // 0..3 ; also does hh+4
        float y1a = 0.f, y2a = 0.f, y1b = 0.f, y2b = 0.f;
        #pragma unroll
        for (int kh = 0; kh < 7; kh++) {
            #pragma unroll
            for (int kw = 0; kw < 7; kw++) {
                float w0c = sw[kh * 7 + kw];
                float w1c = sw[49 + kh * 7 + kw];
                float4 ma = smaps[hh + kh][w + kw];
                float4 mc = smaps[hh + 4 + kh][w + kw];
                y1a = fmaf(ma.x, w0c, fmaf(ma.y, w1c, y1a));
                y2a = fmaf(ma.z, w0c, fmaf(ma.w, w1c, y2a));
                y1b = fmaf(mc.x, w0c, fmaf(mc.y, w1c, y1b));
                y2b = fmaf(mc.z, w0c, fmaf(mc.w, w1c, y2b));
            }
        }
        float scale = rsqrtf(__ldg(var) + 1e-5f) * __ldg(gamma);
        float bias  = __ldg(beta) - __ldg(mean) * scale;
        y1a = fmaxf(fmaf(y1a, scale, bias), 0.f);
        y2a = fmaxf(fmaf(y2a, scale, bias), 0.f);
        y1b = fmaxf(fmaf(y1b, scale, bias), 0.f);
        y2b = fmaxf(fmaf(y2b, scale, bias), 0.f);
        sa1[hh][w]     = 1.0f / (1.0f + expf(-y1a));
        sa2[hh][w]     = 1.0f / (1.0f + expf(-y2a));
        sa1[hh + 4][w] = 1.0f / (1.0f + expf(-y1b));
        sa2[hh + 4][w] = 1.0f / (1.0f + expf(-y2b));
    }
    __syncthreads();

    // --- phase 2: channel loop, 2-way channel split ---
    int half = t >> 7;                      // 0 or 1
    int gi   = t & 127;                     // float4-group in tile
    int r    = gi >> 4;                     // row 0..7
    int c4   = gi & 15;                     // float4 col 0..15

    float a1v[4], a2v[4];
    #pragma unroll
    for (int j = 0; j < 4; j++) {
        a1v[j] = sa1[r][c4 * 4 + j];
        a2v[j] = sa2[r][c4 * 4 + j];
    }

    unsigned long long mask = g_mask[b] >> (half * 32);
    size_t base4 = ((size_t)b * C_ * HW + (h0 + r) * W_ + w0 + c4 * 4) >> 2;
    const float4* xp = (const float4*)x + base4 + half * 32 * (HW / 4);
    float4* op = (float4*)out + base4 + half * 32 * (HW / 4);

    #pragma unroll 8
    for (int c = 0; c < 32; c++) {
        bool rel = (mask >> c) & 1ull;
        float4 v = __ldg(xp + c * (HW / 4));
        float4 o;
        o.x = v.x * (rel ? a1v[0] : a2v[0]);
        o.y = v.y * (rel ? a1v[1] : a2v[1]);
        o.z = v.z * (rel ? a1v[2] : a2v[2]);
        o.w = v.w * (rel ? a1v[3] : a2v[3]);
        op[c * (HW / 4)] = o;
    }
}

// ---------------------------------------------------------------------------
extern "C" void kernel_launch(void* const* d_in, const int* in_sizes, int n_in,
                              void* d_out, int out_size) {
    const float* x     = (const float*)d_in[0];
    const float* M     = (const float*)d_in[1];
    const float* cw    = (const float*)d_in[2];
    const float* gamma = (const float*)d_in[3];
    const float* beta  = (const float*)d_in[4];
    const float* mean  = (const float*)d_in[5];
    const float* var   = (const float*)d_in[6];
    float* out = (float*)d_out;

    reduce_kernel<<<B_ * 32, 256>>>(x, M);                      // 1024 CTAs
    fused_kernel <<<B_ * 32, 256>>>(x, out, cw, gamma, beta, mean, var);
}